// round 15
// baseline (speedup 1.0000x reference)
#include <cuda_runtime.h>
#include <cuda_bf16.h>
#include <cstdint>

// position_encoder: out[b,s,j] = x[b,s,j] + (j even ? sin : cos)(s / 10000^((j+1)/1024))
// B=4, S=8192, D=1024, fp32.
// R8 shell widened to 256-bit global accesses (sm_103a .v8.b32):
// thread = (row, 8-col group), block = 512 threads = 4 rows, grid 2048.
// 4 batch loads front-batched as LDG.256; adds; STG.256. Halves memory
// instruction count per byte, doubles per-thread in-flight bytes.

#define PE_S     8192
#define PE_D     1024
#define PE_B     4
#define PE_ROWS  4                 // rows per block
#define PE_D8    (PE_D / 8)        // 128 eight-col groups per row

struct PETab { double fd[PE_D]; };

constexpr double cexp_small(double t) {
    double r = 1.0;
    for (int k = 24; k >= 1; --k) r = 1.0 + t * r / (double)k;
    return r;
}
constexpr PETab make_tab() {
    PETab t{};
    const double kexp = 13.287712379549449 / 1024.0;  // log2(10000)/1024
    const double ln2  = 0.6931471805599453;
    for (int j = 0; j < PE_D; ++j) {
        const double e = (double)(j + 1) * kexp;
        const int    n = (int)e;
        const double f = e - (double)n;
        double v = cexp_small(-f * ln2);              // 2^-frac
        for (int i = 0; i < n; ++i) v *= 0.5;         // * 2^-int (exact)
        t.fd[j] = v;
    }
    return t;
}
__device__ constexpr PETab g_tab = make_tab();

struct F8 { float f[8]; };

__device__ __forceinline__ F8 ldg256(const float* p) {
    F8 v;
    asm("ld.global.nc.v8.b32 {%0,%1,%2,%3,%4,%5,%6,%7}, [%8];"
        : "=f"(v.f[0]), "=f"(v.f[1]), "=f"(v.f[2]), "=f"(v.f[3]),
          "=f"(v.f[4]), "=f"(v.f[5]), "=f"(v.f[6]), "=f"(v.f[7])
        : "l"(p));
    return v;
}
__device__ __forceinline__ void stg256(float* p, const F8& v) {
    asm volatile("st.global.v8.b32 [%0], {%1,%2,%3,%4,%5,%6,%7,%8};"
                 :: "l"(p),
                    "f"(v.f[0]), "f"(v.f[1]), "f"(v.f[2]), "f"(v.f[3]),
                    "f"(v.f[4]), "f"(v.f[5]), "f"(v.f[6]), "f"(v.f[7])
                 : "memory");
}

__global__ __launch_bounds__(512)
void position_encoder_kernel(const float* __restrict__ x, float* __restrict__ out) {
    const unsigned d8 = threadIdx.x & (PE_D8 - 1);    // 0..127 -> 8-col group
    const unsigned r  = threadIdx.x >> 7;             // 0..3   -> row in block
    const unsigned s  = blockIdx.x * PE_ROWS + r;     // global row
    const unsigned j0 = d8 * 8;

    // pos for (s, j0..j0+7): even cols sin, odd cols cos (fp64 theta -> fp32)
    const double sd = (double)s;
    F8 p;
#pragma unroll
    for (int c = 0; c < 8; c += 2) {
        float sn, cn;
        sincosf((float)(sd * g_tab.fd[j0 + c]), &sn, &cn);
        p.f[c] = sn;                                   // even col: sin
        p.f[c + 1] = cosf((float)(sd * g_tab.fd[j0 + c + 1]));  // odd col: cos
    }

    const size_t bstride = (size_t)PE_S * PE_D;       // floats per batch
    const size_t base    = (size_t)s * PE_D + j0;
    const float* __restrict__ xp = x   + base;
    float* __restrict__       op = out + base;

    // front-batch the 4 batch loads (256-bit), add, store (256-bit)
    F8 v[PE_B];
#pragma unroll
    for (int b = 0; b < PE_B; b++) v[b] = ldg256(xp + (size_t)b * bstride);
#pragma unroll
    for (int b = 0; b < PE_B; b++)
#pragma unroll
        for (int c = 0; c < 8; c++) v[b].f[c] += p.f[c];
#pragma unroll
    for (int b = 0; b < PE_B; b++) stg256(op + (size_t)b * bstride, v[b]);
}

extern "C" void kernel_launch(void* const* d_in, const int* in_sizes, int n_in,
                              void* d_out, int out_size) {
    (void)in_sizes; (void)n_in; (void)out_size;
    const float* x = (const float*)d_in[0];
    float* out = (float*)d_out;
    position_encoder_kernel<<<PE_S / PE_ROWS, 512>>>(x, out);
}

// round 16
// speedup vs baseline: 1.0787x; 1.0787x over previous
#include <cuda_runtime.h>
#include <cuda_bf16.h>

// position_encoder: out[b,s,j] = x[b,s,j] + (j even ? sin : cos)(s / 10000^((j+1)/1024))
// B=4, S=8192, D=1024, fp32.
// FINAL (session-optimal, benched 45.536us deterministically 3x):
// 512-thread blocks, 2 rows/block (thread = row x col4), direct per-row
// sincosf seeding from fp64 theta (compile-time fd table), 4 batch-strided
// float4 loads front-batched, 4 adds, 4 stores.

#define PE_S     8192
#define PE_D     1024
#define PE_B     4
#define PE_ROWS  2                 // rows per block
#define PE_D4    (PE_D / 4)        // 256 float4 per row

struct PETab { double fd[PE_D]; };

constexpr double cexp_small(double t) {
    double r = 1.0;
    for (int k = 24; k >= 1; --k) r = 1.0 + t * r / (double)k;
    return r;
}
constexpr PETab make_tab() {
    PETab t{};
    const double kexp = 13.287712379549449 / 1024.0;  // log2(10000)/1024
    const double ln2  = 0.6931471805599453;
    for (int j = 0; j < PE_D; ++j) {
        const double e = (double)(j + 1) * kexp;
        const int    n = (int)e;
        const double f = e - (double)n;
        double v = cexp_small(-f * ln2);              // 2^-frac
        for (int i = 0; i < n; ++i) v *= 0.5;         // * 2^-int (exact)
        t.fd[j] = v;
    }
    return t;
}
__device__ constexpr PETab g_tab = make_tab();

__global__ __launch_bounds__(512, 3)
void position_encoder_kernel(const float4* __restrict__ x, float4* __restrict__ out) {
    const unsigned d4 = threadIdx.x & (PE_D4 - 1);    // 0..255 -> column group
    const unsigned r  = threadIdx.x >> 8;             // 0..1   -> row within block
    const unsigned s  = blockIdx.x * PE_ROWS + r;     // global row
    const unsigned j0 = d4 * 4;

    // pos vector for (s, j0..j0+3): fp64 theta -> accurate fp32 sincos
    float sn[4], cs[4];
#pragma unroll
    for (int c = 0; c < 4; c++)
        sincosf((float)((double)s * g_tab.fd[j0 + c]), &sn[c], &cs[c]);
    const float4 p = make_float4(sn[0], cs[1], sn[2], cs[3]);

    const unsigned bstride = (unsigned)PE_S * PE_D4;  // float4 per batch
    const unsigned base    = s * PE_D4 + d4;
    const float4* __restrict__ xp = x   + base;
    float4* __restrict__       op = out + base;

    // front-batch the 4 batch loads, then add, then store
    float4 v[PE_B];
#pragma unroll
    for (int b = 0; b < PE_B; b++) v[b] = xp[(size_t)b * bstride];
#pragma unroll
    for (int b = 0; b < PE_B; b++) {
        v[b].x += p.x; v[b].y += p.y; v[b].z += p.z; v[b].w += p.w;
    }
#pragma unroll
    for (int b = 0; b < PE_B; b++) op[(size_t)b * bstride] = v[b];
}

extern "C" void kernel_launch(void* const* d_in, const int* in_sizes, int n_in,
                              void* d_out, int out_size) {
    (void)in_sizes; (void)n_in; (void)out_size;
    const float4* x = (const float4*)d_in[0];
    float4* out = (float4*)d_out;
    position_encoder_kernel<<<PE_S / PE_ROWS, 512>>>(x, out);
}